// round 13
// baseline (speedup 1.0000x reference)
#include <cuda_runtime.h>

#define FULL 0xffffffffu
constexpr int NW = 8;     // warps per block
constexpr int SPW = 2;    // samples per warp (one pair)

// per-sample-slot activation offsets (floats); ANF overlays AV
constexpr int FSP = 0;    // factors, 6 rows stride 8 (48)
constexpr int AU  = 48;   // u / h2, 6 rows stride 36 (224)
constexpr int AV  = 272;  // v (224); ANF overlays (192)
constexpr int ANF = 272;
constexpr int ADJ = 496;  // adjacency rows stride 8 (48)
constexpr int ASP = 544;  // structured / pred rows stride 8 (48)
constexpr int ACT = 592;

__device__ __forceinline__ float sigm(float x) { return 1.0f / (1.0f + __expf(-x)); }

// 16-lane reduction (lanes >= 16 must hold 0)
__device__ __forceinline__ float wsum16(float t) {
#pragma unroll
    for (int o = 8; o; o >>= 1) t += __shfl_xor_sync(FULL, t, o);
    return t;
}

#define FMA4V(acc, vec, wv)                        \
    acc = fmaf((vec).x, (wv).x, acc);              \
    acc = fmaf((vec).y, (wv).y, acc);              \
    acc = fmaf((vec).z, (wv).z, acc);              \
    acc = fmaf((vec).w, (wv).w, acc);

#define LD4(arr, dst, off)                                        \
    { float4 _a = *(const float4*)&(arr)[off];                    \
      (dst)[0] = _a.x; (dst)[1] = _a.y; (dst)[2] = _a.z; (dst)[3] = _a.w; }

#define DOT6S(acc, r4, r2, wc)                     \
    acc = fmaf((r4).x, (wc)[0], acc);              \
    acc = fmaf((r4).y, (wc)[1], acc);              \
    acc = fmaf((r4).z, (wc)[2], acc);              \
    acc = fmaf((r4).w, (wc)[3], acc);              \
    acc = fmaf((r2).x, (wc)[4], acc);              \
    acc = fmaf((r2).y, (wc)[5], acc);

#define DOT6(acc, r4, r2, q4, q2)                  \
    acc = fmaf((r4).x, (q4).x, acc);               \
    acc = fmaf((r4).y, (q4).y, acc);               \
    acc = fmaf((r4).z, (q4).z, acc);               \
    acc = fmaf((r4).w, (q4).w, acc);               \
    acc = fmaf((r2).x, (q2).x, acc);               \
    acc = fmaf((r2).y, (q2).y, acc);

__global__ __launch_bounds__(NW * 32, 4) void cad_kernel(
    const float* __restrict__ factors,
    const float* __restrict__ Wn,  const float* __restrict__ bn,
    const float* __restrict__ We1, const float* __restrict__ be1,
    const float* __restrict__ We2, const float* __restrict__ be2,
    const float* __restrict__ Wd1, const float* __restrict__ bd1,
    const float* __restrict__ Wd2, const float* __restrict__ bd2,
    const float* __restrict__ Wd3, const float* __restrict__ bd3,
    const float* __restrict__ Ws1, const float* __restrict__ bs1,
    const float* __restrict__ Ws2, const float* __restrict__ bs2,
    const float* __restrict__ Ws3, const float* __restrict__ bs3,
    float* __restrict__ out, int Btot)
{
    __shared__ __align__(16) float WuS[192], WvS[192];
    __shared__ __align__(16) float wd1S[192];
    __shared__ __align__(16) float buS[32], bvS[32];
    __shared__ __align__(16) float wd2T[32 * 36];
    __shared__ __align__(16) float wd3F[6 * 36];
    __shared__ __align__(16) float ws1T[32 * 20];
    __shared__ __align__(16) float ws2T[16 * 36];
    __shared__ __align__(16) float we2S[32];
    __shared__ float bd1S[32], bd2S[32], bs1S[32];
    __shared__ float bs2S[16], ws3S[16], bd3S[8], scal[2];
    __shared__ __align__(16) float act[NW][2][ACT];

    const int tid = threadIdx.x;

    // ---- composed edge weights: Wu = Wn@We1[:32], Wv = Wn@We1[32:] ----
    if (tid < 192) {
        int f = tid >> 5, h = tid & 31;
        float au = 0.0f, av = 0.0f;
#pragma unroll 4
        for (int k = 0; k < 32; k++) {
            float wn = Wn[f * 32 + k];
            au = fmaf(wn, We1[k * 32 + h], au);
            av = fmaf(wn, We1[(32 + k) * 32 + h], av);
        }
        WuS[f * 32 + h] = au;
        WvS[f * 32 + h] = av;
        wd1S[f * 32 + h] = Wd1[f * 32 + h];
    }
    if (tid < 32) {
        float bu = be1[tid], bv = 0.0f;
#pragma unroll 4
        for (int k = 0; k < 32; k++) {
            float b = bn[k];
            bu = fmaf(b, We1[k * 32 + tid], bu);
            bv = fmaf(b, We1[(32 + k) * 32 + tid], bv);
        }
        buS[tid] = bu; bvS[tid] = bv;
    }
    for (int idx = tid; idx < 1024; idx += NW * 32) {
        int k = idx >> 5, l = idx & 31;
        wd2T[l * 36 + k] = Wd2[idx];
    }
    for (int idx = tid; idx < 576; idx += NW * 32) {
        int k = idx >> 5, l = idx & 31;
        ws1T[l * 20 + k] = Ws1[idx];
    }
    for (int idx = tid; idx < 512; idx += NW * 32) {
        int k = idx >> 4, m = idx & 15;
        ws2T[m * 36 + k] = Ws2[idx];
    }
    for (int idx = tid; idx < 192; idx += NW * 32) {
        int k3 = idx / 6, f3 = idx - k3 * 6;
        wd3F[f3 * 36 + k3] = Wd3[idx];
    }
    if (tid < 32) {
        we2S[tid] = We2[tid];
        bd1S[tid] = bd1[tid]; bd2S[tid] = bd2[tid]; bs1S[tid] = bs1[tid];
    }
    if (tid < 16) { bs2S[tid] = bs2[tid]; ws3S[tid] = Ws3[tid]; }
    if (tid < 6)  { bd3S[tid] = bd3[tid]; }
    if (tid == 0) { scal[0] = be2[0]; scal[1] = bs3[0]; }
    __syncthreads();

    const int lane = tid & 31;
    const int w = tid >> 5;

    const int i1 = lane / 6, j1 = lane - i1 * 6;   // element e = lane
    const int j2 = (lane < 4) ? lane + 2 : 2;      // element 32+lane -> (5, j2)

    // adjacency 30-edge map (lanes 30,31 shadow lane 29; no stores)
    const int la = (lane < 30) ? lane : 29;
    const int ia = la / 5;
    const int jt = la - ia * 5;
    const int ja = jt + (jt >= ia ? 1 : 0);

    // pred leftover map: lanes 0..7 -> (p = lane>>2, e = 32 + (lane&3))
    const int pL = (lane >> 2) & 1;
    const int j2x = 2 + (lane & 3);

    const int b0 = (blockIdx.x * NW + w) * SPW;
    if (b0 >= Btot) return;
    const bool v1 = (b0 + 1) < Btot;

    // ---- stage factors ----
#pragma unroll
    for (int p = 0; p < 2; p++) {
        float* A = act[w][p];
        const float* fb = factors + (size_t)(p ? (v1 ? b0 + 1 : b0) : b0) * 36;
        A[FSP + i1 * 8 + j1] = fb[lane];
        if (lane < 4) A[FSP + 40 + j2] = fb[32 + lane];
    }
    __syncwarp();

    // ---- u,v via composed weights ----
    {
        float wuC[6], wvC[6];
#pragma unroll
        for (int f = 0; f < 6; f++) {
            wuC[f] = WuS[f * 32 + lane];
            wvC[f] = WvS[f * 32 + lane];
        }
        float bul = buS[lane], bvl = bvS[lane];
#pragma unroll
        for (int p = 0; p < 2; p++) {
            float* A = act[w][p];
#pragma unroll
            for (int i = 0; i < 6; i++) {
                float4 f4 = *(const float4*)&A[FSP + i * 8];
                float2 f2 = *(const float2*)&A[FSP + i * 8 + 4];
                float ui = bul, vi = bvl;
                DOT6S(ui, f4, f2, wuC);
                DOT6S(vi, f4, f2, wvC);
                A[AU + i * 36 + lane] = ui;
                A[AV + i * 36 + lane] = vi;
            }
        }
    }
    __syncwarp();

    // ---- adjacency: lane = one of 30 off-diagonal edges ----
    {
        float acc[2] = {0.0f, 0.0f};
#pragma unroll
        for (int t = 0; t < 8; t++) {
            float4 w2 = *(const float4*)&we2S[4 * t];
#pragma unroll
            for (int p = 0; p < 2; p++) {
                float* A = act[w][p];
                float4 a1 = *(const float4*)&A[AU + ia * 36 + 4 * t];
                float4 b1 = *(const float4*)&A[AV + ja * 36 + 4 * t];
                acc[p] = fmaf(fmaxf(a1.x + b1.x, 0.0f), w2.x, acc[p]);
                acc[p] = fmaf(fmaxf(a1.y + b1.y, 0.0f), w2.y, acc[p]);
                acc[p] = fmaf(fmaxf(a1.z + b1.z, 0.0f), w2.z, acc[p]);
                acc[p] = fmaf(fmaxf(a1.w + b1.w, 0.0f), w2.w, acc[p]);
            }
        }
        float be2v = scal[0];
#pragma unroll
        for (int p = 0; p < 2; p++) {
            float* A = act[w][p];
            float av = sigm(acc[p] + be2v);
            if (lane < 30) A[ADJ + ia * 8 + ja] = av;
            if (lane < 6)  A[ADJ + lane * 9] = 0.0f;   // diagonal (i*8+i)
        }
    }
    __syncwarp();

    // ---- coalesced adj output from staging tile ----
#pragma unroll
    for (int p = 0; p < 2; p++) {
        if (p == 0 || v1) {
            float* A = act[w][p];
            float* oa = out + (size_t)(b0 + p) * 36;
            oa[lane] = A[ADJ + i1 * 8 + j1];
            if (lane < 4) oa[32 + lane] = A[ADJ + 40 + j2];
        }
    }

    // ---- structured (lane = (n=i1, i=j1)) ----
#pragma unroll
    for (int p = 0; p < 2; p++) {
        float* A = act[w][p];
        float4 ra4 = *(const float4*)&A[ADJ + j1 * 8];
        float2 ra2 = *(const float2*)&A[ADJ + j1 * 8 + 4];
        float4 rf4 = *(const float4*)&A[FSP + i1 * 8];
        float2 rf2 = *(const float2*)&A[FSP + i1 * 8 + 4];
        float sv = 0.0f;
        DOT6(sv, ra4, ra2, rf4, rf2);
        A[ASP + i1 * 8 + j1] = sv;
        if (lane < 4) {
            float4 qa4 = *(const float4*)&A[ADJ + j2 * 8];
            float2 qa2 = *(const float2*)&A[ADJ + j2 * 8 + 4];
            float4 qf4 = *(const float4*)&A[FSP + 40];
            float2 qf2 = *(const float2*)&A[FSP + 44];
            float sv2 = 0.0f;
            DOT6(sv2, qa4, qa2, qf4, qf2);
            A[ASP + 40 + j2] = sv2;
        }
    }
    __syncwarp();

    // ---- h1 (lane = hidden) ----
    {
        float wd1c[6];
#pragma unroll
        for (int f = 0; f < 6; f++) wd1c[f] = wd1S[f * 32 + lane];
        float bd1l = bd1S[lane];
#pragma unroll
        for (int p = 0; p < 2; p++) {
            float* A = act[w][p];
#pragma unroll
            for (int n = 0; n < 6; n++) {
                float4 s4 = *(const float4*)&A[ASP + n * 8];
                float2 s2 = *(const float2*)&A[ASP + n * 8 + 4];
                float acc = bd1l;
                DOT6S(acc, s4, s2, wd1c);
                A[ANF + n * 32 + lane] = fmaxf(acc, 0.0f);
            }
        }
    }
    __syncwarp();

    // ---- h2 interchanged ----
    {
        float acc[2][6];
        float bd2l = bd2S[lane];
#pragma unroll
        for (int p = 0; p < 2; p++)
#pragma unroll
            for (int n = 0; n < 6; n++) acc[p][n] = bd2l;
#pragma unroll
        for (int t = 0; t < 8; t++) {
            float4 wv2 = *(const float4*)&wd2T[lane * 36 + 4 * t];
#pragma unroll
            for (int p = 0; p < 2; p++) {
                float* A = act[w][p];
#pragma unroll
                for (int n = 0; n < 6; n++) {
                    float4 hv = *(const float4*)&A[ANF + n * 32 + 4 * t];
                    FMA4V(acc[p][n], hv, wv2);
                }
            }
        }
#pragma unroll
        for (int p = 0; p < 2; p++) {
            float* A = act[w][p];
#pragma unroll
            for (int n = 0; n < 6; n++)
                A[AU + n * 36 + lane] = fmaxf(acc[p][n], 0.0f);
        }
    }
    __syncwarp();

    // ---- pred: main 32 elems x2p + 8 leftover on lanes 0..7 ----
    {
        float pa[2] = {0.0f, 0.0f};
        float pbx = 0.0f;
        const float* Ax = act[w][pL];
#pragma unroll
        for (int t = 0; t < 8; t++) {
            float4 w3a = *(const float4*)&wd3F[j1 * 36 + 4 * t];
#pragma unroll
            for (int p = 0; p < 2; p++) {
                float* A = act[w][p];
                float4 hv = *(const float4*)&A[AU + i1 * 36 + 4 * t];
                FMA4V(pa[p], hv, w3a);
            }
            float4 h5 = *(const float4*)&Ax[AU + 5 * 36 + 4 * t];
            float4 w3b = *(const float4*)&wd3F[j2x * 36 + 4 * t];
            FMA4V(pbx, h5, w3b);
        }
        float bd3l = bd3S[j1];
        float bd3x = bd3S[j2x];
#pragma unroll
        for (int p = 0; p < 2; p++) {
            float* A = act[w][p];
            float p1 = pa[p] + bd3l;
            A[ASP + i1 * 8 + j1] = p1;
            if (p == 0 || v1) {
                float* op = out + (size_t)Btot * 36 + (size_t)(b0 + p) * 36;
                op[lane] = p1;
            }
        }
        if (lane < 8) {
            float p2 = pbx + bd3x;
            act[w][pL][ASP + 40 + j2x] = p2;
            if (pL == 0 || v1)
                out[(size_t)Btot * 36 + (size_t)(b0 + pL) * 36 + 32 + (lane & 3)] = p2;
        }
    }
    __syncwarp();

    // ---- scorer layer 1 ----
    {
        float ws1c[18];
#pragma unroll
        for (int t = 0; t < 4; t++) LD4(ws1T, ws1c + 4 * t, lane * 20 + 4 * t);
        {
            float2 a = *(const float2*)&ws1T[lane * 20 + 16];
            ws1c[16] = a.x; ws1c[17] = a.y;
        }
        float bs1l = bs1S[lane];
#pragma unroll
        for (int p = 0; p < 2; p++) {
            float* A = act[w][p];
#pragma unroll
            for (int n = 0; n < 6; n++) {
                float4 f4 = *(const float4*)&A[FSP + n * 8];
                float2 f2 = *(const float2*)&A[FSP + n * 8 + 4];
                float4 p4 = *(const float4*)&A[ASP + n * 8];
                float2 p2 = *(const float2*)&A[ASP + n * 8 + 4];
                float fk[6] = {f4.x, f4.y, f4.z, f4.w, f2.x, f2.y};
                float pk[6] = {p4.x, p4.y, p4.z, p4.w, p2.x, p2.y};
                float acc = bs1l;
#pragma unroll
                for (int k = 0; k < 6; k++) {
                    acc = fmaf(fk[k], ws1c[k], acc);
                    acc = fmaf(pk[k], ws1c[6 + k], acc);
                    acc = fmaf(fabsf(fk[k] - pk[k]), ws1c[12 + k], acc);
                }
                A[ANF + n * 32 + lane] = fmaxf(acc, 0.0f);
            }
        }
    }
    __syncwarp();

    // ---- scorer layers 2+3 ----
    {
        float acc[2][6];
        float bs2l = bs2S[lane & 15];
#pragma unroll
        for (int p = 0; p < 2; p++)
#pragma unroll
            for (int n = 0; n < 6; n++) acc[p][n] = bs2l;
#pragma unroll
        for (int t = 0; t < 8; t++) {
            float4 wv2 = *(const float4*)&ws2T[(lane & 15) * 36 + 4 * t];
#pragma unroll
            for (int p = 0; p < 2; p++) {
                float* A = act[w][p];
#pragma unroll
                for (int n = 0; n < 6; n++) {
                    float4 sv = *(const float4*)&A[ANF + n * 32 + 4 * t];
                    FMA4V(acc[p][n], sv, wv2);
                }
            }
        }
        float ws3l = (lane < 16) ? ws3S[lane] : 0.0f;
        float bs3v = scal[1];
#pragma unroll
        for (int p = 0; p < 2; p++) {
            float ssum = 0.0f;
#pragma unroll
            for (int n = 0; n < 6; n++) {
                float tt = fmaxf(acc[p][n], 0.0f) * ws3l;  // lanes >= 16: 0
                ssum += sigm(wsum16(tt) + bs3v);
            }
            if (lane == 0 && (p == 0 || v1))
                out[(size_t)Btot * 72 + (b0 + p)] = ssum * (1.0f / 6.0f);
        }
    }
}

extern "C" void kernel_launch(void* const* d_in, const int* in_sizes, int n_in,
                              void* d_out, int out_size) {
    const float* p[19];
    for (int i = 0; i < 19; i++) p[i] = (const float*)d_in[i];
    int Btot = in_sizes[0] / 36;
    int per_block = NW * SPW;
    int blocks = (Btot + per_block - 1) / per_block;
    cad_kernel<<<blocks, NW * 32>>>(
        p[0], p[1], p[2], p[3], p[4], p[5], p[6], p[7], p[8], p[9], p[10],
        p[11], p[12], p[13], p[14], p[15], p[16], p[17], p[18],
        (float*)d_out, Btot);
}

// round 14
// speedup vs baseline: 1.1076x; 1.1076x over previous
#include <cuda_runtime.h>

#define FULL 0xffffffffu
constexpr int NW = 8;     // warps per block
constexpr int SPW = 8;    // samples per warp
constexpr int PAIRS = SPW / 2;

// per-sample-slot activation offsets (floats); ANF overlays AV
constexpr int FSP = 0;    // factors, 6 rows stride 8 (48)
constexpr int AU  = 48;   // u / h2, 6 rows stride 36 (224)
constexpr int AV  = 272;  // v (224); ANF overlays (192)
constexpr int ANF = 272;
constexpr int ADJ = 496;  // adjacency rows stride 8 (48)
constexpr int ASP = 544;  // structured / pred rows stride 8 (48)
constexpr int ACT = 592;

__device__ __forceinline__ float sigm(float x) { return 1.0f / (1.0f + __expf(-x)); }

// 16-lane reduction (lanes >= 16 must hold 0)
__device__ __forceinline__ float wsum16(float t) {
#pragma unroll
    for (int o = 8; o; o >>= 1) t += __shfl_xor_sync(FULL, t, o);
    return t;
}

#define FMA4V(acc, vec, wv)                        \
    acc = fmaf((vec).x, (wv).x, acc);              \
    acc = fmaf((vec).y, (wv).y, acc);              \
    acc = fmaf((vec).z, (wv).z, acc);              \
    acc = fmaf((vec).w, (wv).w, acc);

#define LD4(arr, dst, off)                                        \
    { float4 _a = *(const float4*)&(arr)[off];                    \
      (dst)[0] = _a.x; (dst)[1] = _a.y; (dst)[2] = _a.z; (dst)[3] = _a.w; }

#define DOT6S(acc, r4, r2, wc)                     \
    acc = fmaf((r4).x, (wc)[0], acc);              \
    acc = fmaf((r4).y, (wc)[1], acc);              \
    acc = fmaf((r4).z, (wc)[2], acc);              \
    acc = fmaf((r4).w, (wc)[3], acc);              \
    acc = fmaf((r2).x, (wc)[4], acc);              \
    acc = fmaf((r2).y, (wc)[5], acc);

#define DOT6(acc, r4, r2, q4, q2)                  \
    acc = fmaf((r4).x, (q4).x, acc);               \
    acc = fmaf((r4).y, (q4).y, acc);               \
    acc = fmaf((r4).z, (q4).z, acc);               \
    acc = fmaf((r4).w, (q4).w, acc);               \
    acc = fmaf((r2).x, (q2).x, acc);               \
    acc = fmaf((r2).y, (q2).y, acc);

__global__ __launch_bounds__(NW * 32, 4) void cad_kernel(
    const float* __restrict__ factors,
    const float* __restrict__ Wn,  const float* __restrict__ bn,
    const float* __restrict__ We1, const float* __restrict__ be1,
    const float* __restrict__ We2, const float* __restrict__ be2,
    const float* __restrict__ Wd1, const float* __restrict__ bd1,
    const float* __restrict__ Wd2, const float* __restrict__ bd2,
    const float* __restrict__ Wd3, const float* __restrict__ bd3,
    const float* __restrict__ Ws1, const float* __restrict__ bs1,
    const float* __restrict__ Ws2, const float* __restrict__ bs2,
    const float* __restrict__ Ws3, const float* __restrict__ bs3,
    float* __restrict__ out, int Btot)
{
    __shared__ __align__(16) float WuS[192], WvS[192];
    __shared__ __align__(16) float wd1S[192];
    __shared__ __align__(16) float buS[32], bvS[32];
    __shared__ __align__(16) float wd2T[32 * 36];
    __shared__ __align__(16) float wd3F[6 * 36];
    __shared__ __align__(16) float ws1T[32 * 20];
    __shared__ __align__(16) float ws2T[16 * 36];
    __shared__ __align__(16) float we2S[32];
    __shared__ float bd1S[32], bd2S[32], bs1S[32];
    __shared__ float bs2S[16], ws3S[16], bd3S[8], scal[2];
    __shared__ __align__(16) float act[NW][2][ACT];

    const int tid = threadIdx.x;

    // ---- composed edge weights: Wu = Wn@We1[:32], Wv = Wn@We1[32:] ----
    if (tid < 192) {
        int f = tid >> 5, h = tid & 31;
        float au = 0.0f, av = 0.0f;
#pragma unroll 4
        for (int k = 0; k < 32; k++) {
            float wn = Wn[f * 32 + k];
            au = fmaf(wn, We1[k * 32 + h], au);
            av = fmaf(wn, We1[(32 + k) * 32 + h], av);
        }
        WuS[f * 32 + h] = au;
        WvS[f * 32 + h] = av;
        wd1S[f * 32 + h] = Wd1[f * 32 + h];
    }
    if (tid < 32) {
        float bu = be1[tid], bv = 0.0f;
#pragma unroll 4
        for (int k = 0; k < 32; k++) {
            float b = bn[k];
            bu = fmaf(b, We1[k * 32 + tid], bu);
            bv = fmaf(b, We1[(32 + k) * 32 + tid], bv);
        }
        buS[tid] = bu; bvS[tid] = bv;
    }
    for (int idx = tid; idx < 1024; idx += NW * 32) {
        int k = idx >> 5, l = idx & 31;
        wd2T[l * 36 + k] = Wd2[idx];
    }
    for (int idx = tid; idx < 576; idx += NW * 32) {
        int k = idx >> 5, l = idx & 31;
        ws1T[l * 20 + k] = Ws1[idx];
    }
    for (int idx = tid; idx < 512; idx += NW * 32) {
        int k = idx >> 4, m = idx & 15;
        ws2T[m * 36 + k] = Ws2[idx];
    }
    for (int idx = tid; idx < 192; idx += NW * 32) {
        int k3 = idx / 6, f3 = idx - k3 * 6;
        wd3F[f3 * 36 + k3] = Wd3[idx];
    }
    if (tid < 32) {
        we2S[tid] = We2[tid];
        bd1S[tid] = bd1[tid]; bd2S[tid] = bd2[tid]; bs1S[tid] = bs1[tid];
    }
    if (tid < 16) { bs2S[tid] = bs2[tid]; ws3S[tid] = Ws3[tid]; }
    if (tid < 6)  { bd3S[tid] = bd3[tid]; }
    if (tid == 0) { scal[0] = be2[0]; scal[1] = bs3[0]; }
    __syncthreads();

    const int lane = tid & 31;
    const int w = tid >> 5;

    const int i1 = lane / 6, j1 = lane - i1 * 6;   // element e = lane
    const int j2 = (lane < 4) ? lane + 2 : 2;      // element 32+lane -> (5, j2)

    // adjacency 30-edge map (lanes 30,31 shadow lane 29; no stores)
    const int la = (lane < 30) ? lane : 29;
    const int ia = la / 5;
    const int jt = la - ia * 5;
    const int ja = jt + (jt >= ia ? 1 : 0);

    // pred leftover map: lanes 0..7 -> (p = lane>>2, e = 32 + (lane&3))
    const int pL = (lane >> 2) & 1;
    const int j2x = 2 + (lane & 3);

#pragma unroll 1
    for (int it = 0; it < PAIRS; it++) {
        const int b0 = ((blockIdx.x * NW + w) * SPW) + 2 * it;
        if (b0 < Btot) {
            const bool v1 = (b0 + 1) < Btot;

            // ---- stage factors ----
#pragma unroll
            for (int p = 0; p < 2; p++) {
                float* A = act[w][p];
                const float* fb = factors + (size_t)(p ? (v1 ? b0 + 1 : b0) : b0) * 36;
                A[FSP + i1 * 8 + j1] = fb[lane];
                if (lane < 4) A[FSP + 40 + j2] = fb[32 + lane];
            }
            __syncwarp();

            // ---- u,v via composed weights ----
            {
                float wuC[6], wvC[6];
#pragma unroll
                for (int f = 0; f < 6; f++) {
                    wuC[f] = WuS[f * 32 + lane];
                    wvC[f] = WvS[f * 32 + lane];
                }
                float bul = buS[lane], bvl = bvS[lane];
#pragma unroll
                for (int p = 0; p < 2; p++) {
                    float* A = act[w][p];
#pragma unroll
                    for (int i = 0; i < 6; i++) {
                        float4 f4 = *(const float4*)&A[FSP + i * 8];
                        float2 f2 = *(const float2*)&A[FSP + i * 8 + 4];
                        float ui = bul, vi = bvl;
                        DOT6S(ui, f4, f2, wuC);
                        DOT6S(vi, f4, f2, wvC);
                        A[AU + i * 36 + lane] = ui;
                        A[AV + i * 36 + lane] = vi;
                    }
                }
            }
            __syncwarp();

            // ---- adjacency: lane = one of 30 off-diagonal edges ----
            {
                float acc[2] = {0.0f, 0.0f};
#pragma unroll
                for (int t = 0; t < 8; t++) {
                    float4 w2 = *(const float4*)&we2S[4 * t];
#pragma unroll
                    for (int p = 0; p < 2; p++) {
                        float* A = act[w][p];
                        float4 a1 = *(const float4*)&A[AU + ia * 36 + 4 * t];
                        float4 b1 = *(const float4*)&A[AV + ja * 36 + 4 * t];
                        acc[p] = fmaf(fmaxf(a1.x + b1.x, 0.0f), w2.x, acc[p]);
                        acc[p] = fmaf(fmaxf(a1.y + b1.y, 0.0f), w2.y, acc[p]);
                        acc[p] = fmaf(fmaxf(a1.z + b1.z, 0.0f), w2.z, acc[p]);
                        acc[p] = fmaf(fmaxf(a1.w + b1.w, 0.0f), w2.w, acc[p]);
                    }
                }
                float be2v = scal[0];
#pragma unroll
                for (int p = 0; p < 2; p++) {
                    float* A = act[w][p];
                    float av = sigm(acc[p] + be2v);
                    if (lane < 30) A[ADJ + ia * 8 + ja] = av;
                    if (lane < 6)  A[ADJ + lane * 9] = 0.0f;   // diagonal
                }
            }
            __syncwarp();

            // ---- coalesced adj output from staging tile ----
#pragma unroll
            for (int p = 0; p < 2; p++) {
                if (p == 0 || v1) {
                    float* A = act[w][p];
                    float* oa = out + (size_t)(b0 + p) * 36;
                    oa[lane] = A[ADJ + i1 * 8 + j1];
                    if (lane < 4) oa[32 + lane] = A[ADJ + 40 + j2];
                }
            }

            // ---- structured (lane = (n=i1, i=j1)) ----
#pragma unroll
            for (int p = 0; p < 2; p++) {
                float* A = act[w][p];
                float4 ra4 = *(const float4*)&A[ADJ + j1 * 8];
                float2 ra2 = *(const float2*)&A[ADJ + j1 * 8 + 4];
                float4 rf4 = *(const float4*)&A[FSP + i1 * 8];
                float2 rf2 = *(const float2*)&A[FSP + i1 * 8 + 4];
                float sv = 0.0f;
                DOT6(sv, ra4, ra2, rf4, rf2);
                A[ASP + i1 * 8 + j1] = sv;
                if (lane < 4) {
                    float4 qa4 = *(const float4*)&A[ADJ + j2 * 8];
                    float2 qa2 = *(const float2*)&A[ADJ + j2 * 8 + 4];
                    float4 qf4 = *(const float4*)&A[FSP + 40];
                    float2 qf2 = *(const float2*)&A[FSP + 44];
                    float sv2 = 0.0f;
                    DOT6(sv2, qa4, qa2, qf4, qf2);
                    A[ASP + 40 + j2] = sv2;
                }
            }
            __syncwarp();

            // ---- h1 (lane = hidden) ----
            {
                float wd1c[6];
#pragma unroll
                for (int f = 0; f < 6; f++) wd1c[f] = wd1S[f * 32 + lane];
                float bd1l = bd1S[lane];
#pragma unroll
                for (int p = 0; p < 2; p++) {
                    float* A = act[w][p];
#pragma unroll
                    for (int n = 0; n < 6; n++) {
                        float4 s4 = *(const float4*)&A[ASP + n * 8];
                        float2 s2 = *(const float2*)&A[ASP + n * 8 + 4];
                        float acc = bd1l;
                        DOT6S(acc, s4, s2, wd1c);
                        A[ANF + n * 32 + lane] = fmaxf(acc, 0.0f);
                    }
                }
            }
            __syncwarp();

            // ---- h2 interchanged ----
            {
                float acc[2][6];
                float bd2l = bd2S[lane];
#pragma unroll
                for (int p = 0; p < 2; p++)
#pragma unroll
                    for (int n = 0; n < 6; n++) acc[p][n] = bd2l;
#pragma unroll
                for (int t = 0; t < 8; t++) {
                    float4 wv2 = *(const float4*)&wd2T[lane * 36 + 4 * t];
#pragma unroll
                    for (int p = 0; p < 2; p++) {
                        float* A = act[w][p];
#pragma unroll
                        for (int n = 0; n < 6; n++) {
                            float4 hv = *(const float4*)&A[ANF + n * 32 + 4 * t];
                            FMA4V(acc[p][n], hv, wv2);
                        }
                    }
                }
#pragma unroll
                for (int p = 0; p < 2; p++) {
                    float* A = act[w][p];
#pragma unroll
                    for (int n = 0; n < 6; n++)
                        A[AU + n * 36 + lane] = fmaxf(acc[p][n], 0.0f);
                }
            }
            __syncwarp();

            // ---- pred: main 32 elems x2p + 8 leftover on lanes 0..7 ----
            {
                float pa[2] = {0.0f, 0.0f};
                float pbx = 0.0f;
                const float* Ax = act[w][pL];
#pragma unroll
                for (int t = 0; t < 8; t++) {
                    float4 w3a = *(const float4*)&wd3F[j1 * 36 + 4 * t];
#pragma unroll
                    for (int p = 0; p < 2; p++) {
                        float* A = act[w][p];
                        float4 hv = *(const float4*)&A[AU + i1 * 36 + 4 * t];
                        FMA4V(pa[p], hv, w3a);
                    }
                    float4 h5 = *(const float4*)&Ax[AU + 5 * 36 + 4 * t];
                    float4 w3b = *(const float4*)&wd3F[j2x * 36 + 4 * t];
                    FMA4V(pbx, h5, w3b);
                }
                float bd3l = bd3S[j1];
                float bd3x = bd3S[j2x];
#pragma unroll
                for (int p = 0; p < 2; p++) {
                    float* A = act[w][p];
                    float p1 = pa[p] + bd3l;
                    A[ASP + i1 * 8 + j1] = p1;
                    if (p == 0 || v1) {
                        float* op = out + (size_t)Btot * 36 + (size_t)(b0 + p) * 36;
                        op[lane] = p1;
                    }
                }
                if (lane < 8) {
                    float p2 = pbx + bd3x;
                    act[w][pL][ASP + 40 + j2x] = p2;
                    if (pL == 0 || v1)
                        out[(size_t)Btot * 36 + (size_t)(b0 + pL) * 36 + 32 + (lane & 3)] = p2;
                }
            }
            __syncwarp();

            // ---- scorer layer 1 ----
            {
                float ws1c[18];
#pragma unroll
                for (int t = 0; t < 4; t++) LD4(ws1T, ws1c + 4 * t, lane * 20 + 4 * t);
                {
                    float2 a = *(const float2*)&ws1T[lane * 20 + 16];
                    ws1c[16] = a.x; ws1c[17] = a.y;
                }
                float bs1l = bs1S[lane];
#pragma unroll
                for (int p = 0; p < 2; p++) {
                    float* A = act[w][p];
#pragma unroll
                    for (int n = 0; n < 6; n++) {
                        float4 f4 = *(const float4*)&A[FSP + n * 8];
                        float2 f2 = *(const float2*)&A[FSP + n * 8 + 4];
                        float4 p4 = *(const float4*)&A[ASP + n * 8];
                        float2 p2 = *(const float2*)&A[ASP + n * 8 + 4];
                        float fk[6] = {f4.x, f4.y, f4.z, f4.w, f2.x, f2.y};
                        float pk[6] = {p4.x, p4.y, p4.z, p4.w, p2.x, p2.y};
                        float acc = bs1l;
#pragma unroll
                        for (int k = 0; k < 6; k++) {
                            acc = fmaf(fk[k], ws1c[k], acc);
                            acc = fmaf(pk[k], ws1c[6 + k], acc);
                            acc = fmaf(fabsf(fk[k] - pk[k]), ws1c[12 + k], acc);
                        }
                        A[ANF + n * 32 + lane] = fmaxf(acc, 0.0f);
                    }
                }
            }
            __syncwarp();

            // ---- scorer layers 2+3 ----
            {
                float acc[2][6];
                float bs2l = bs2S[lane & 15];
#pragma unroll
                for (int p = 0; p < 2; p++)
#pragma unroll
                    for (int n = 0; n < 6; n++) acc[p][n] = bs2l;
#pragma unroll
                for (int t = 0; t < 8; t++) {
                    float4 wv2 = *(const float4*)&ws2T[(lane & 15) * 36 + 4 * t];
#pragma unroll
                    for (int p = 0; p < 2; p++) {
                        float* A = act[w][p];
#pragma unroll
                        for (int n = 0; n < 6; n++) {
                            float4 sv = *(const float4*)&A[ANF + n * 32 + 4 * t];
                            FMA4V(acc[p][n], sv, wv2);
                        }
                    }
                }
                float ws3l = (lane < 16) ? ws3S[lane] : 0.0f;
                float bs3v = scal[1];
#pragma unroll
                for (int p = 0; p < 2; p++) {
                    float ssum = 0.0f;
#pragma unroll
                    for (int n = 0; n < 6; n++) {
                        float tt = fmaxf(acc[p][n], 0.0f) * ws3l;  // lanes >= 16: 0
                        ssum += sigm(wsum16(tt) + bs3v);
                    }
                    if (lane == 0 && (p == 0 || v1))
                        out[(size_t)Btot * 72 + (b0 + p)] = ssum * (1.0f / 6.0f);
                }
            }
            __syncwarp();
        }
    }
}

extern "C" void kernel_launch(void* const* d_in, const int* in_sizes, int n_in,
                              void* d_out, int out_size) {
    const float* p[19];
    for (int i = 0; i < 19; i++) p[i] = (const float*)d_in[i];
    int Btot = in_sizes[0] / 36;
    int per_block = NW * SPW;
    int blocks = (Btot + per_block - 1) / per_block;
    cad_kernel<<<blocks, NW * 32>>>(
        p[0], p[1], p[2], p[3], p[4], p[5], p[6], p[7], p[8], p[9], p[10],
        p[11], p[12], p[13], p[14], p[15], p[16], p[17], p[18],
        (float*)d_out, Btot);
}